// round 2
// baseline (speedup 1.0000x reference)
#include <cuda_runtime.h>

// Problem constants (fixed by the reference: B=2, G=64)
constexpr int G3      = 64 * 64 * 64;   // 262144 voxels per batch
constexpr int NB      = 2;
constexpr int THREADS = 256;

// C_ijkl[b,v] = sum_{m,n,o,p} a[b,m,i,v] a[b,n,j,v] a[b,o,k,v] a[b,p,l,v] C0[m,n,o,p]
// Four staged rank-1 contractions: 972 FMA per voxel.
// One voxel per thread; reg-capped for 3 CTAs/SM (24 warps) to hide FFMA+DRAM latency.
__global__ __launch_bounds__(THREADS, 3)
void alphaC0_42C_kernel(const float* __restrict__ a,
                        const float* __restrict__ c0,
                        float* __restrict__ out)
{
    __shared__ float sc0[81];
    if (threadIdx.x < 81) sc0[threadIdx.x] = c0[threadIdx.x];
    __syncthreads();

    // Flattened (b, voxel) index.
    const long gv = (long)blockIdx.x * THREADS + threadIdx.x;
    const int  b  = (int)(gv / G3);
    const long v  = gv - (long)b * G3;

    // Load the 3x3 per-voxel matrix a[m][i]: a[((b*3+m)*3+i)*G3 + v]
    const float* ap = a + (long)b * 9 * G3 + v;
    float A[9];
#pragma unroll
    for (int mi = 0; mi < 9; ++mi)
        A[mi] = __ldg(ap + (long)mi * G3);

    float* ob = out + (long)b * 81 * G3 + v;

#pragma unroll
    for (int i = 0; i < 3; ++i) {
        // Stage 1: T1[n,o,p] = sum_m A[m,i] * C0[m,n,o,p]
        float T1[27];
#pragma unroll
        for (int nop = 0; nop < 27; ++nop) {
            float s = A[0 * 3 + i] * sc0[nop];
            s = fmaf(A[1 * 3 + i], sc0[27 + nop], s);
            s = fmaf(A[2 * 3 + i], sc0[54 + nop], s);
            T1[nop] = s;
        }
#pragma unroll
        for (int j = 0; j < 3; ++j) {
            // Stage 2: T2[o,p] = sum_n A[n,j] * T1[n,o,p]
            float T2[9];
#pragma unroll
            for (int op = 0; op < 9; ++op) {
                float s = A[0 * 3 + j] * T1[op];
                s = fmaf(A[1 * 3 + j], T1[9 + op], s);
                s = fmaf(A[2 * 3 + j], T1[18 + op], s);
                T2[op] = s;
            }
#pragma unroll
            for (int k = 0; k < 3; ++k) {
                // Stage 3: T3[p] = sum_o A[o,k] * T2[o,p]
                float T3[3];
#pragma unroll
                for (int p = 0; p < 3; ++p) {
                    float s = A[0 * 3 + k] * T2[p];
                    s = fmaf(A[1 * 3 + k], T2[3 + p], s);
                    s = fmaf(A[2 * 3 + k], T2[6 + p], s);
                    T3[p] = s;
                }
#pragma unroll
                for (int l = 0; l < 3; ++l) {
                    // Stage 4: C[i,j,k,l] = sum_p A[p,l] * T3[p]
                    float r = A[0 * 3 + l] * T3[0];
                    r = fmaf(A[1 * 3 + l], T3[1], r);
                    r = fmaf(A[2 * 3 + l], T3[2], r);
                    // Output never re-read: streaming store, fully coalesced.
                    __stcs(ob + (long)(((i * 3 + j) * 3 + k) * 3 + l) * G3, r);
                }
            }
        }
    }
}

extern "C" void kernel_launch(void* const* d_in, const int* in_sizes, int n_in,
                              void* d_out, int out_size)
{
    const float* a   = (const float*)d_in[0];   // alphatensor (2,3,3,64,64,64)
    const float* c0  = (const float*)d_in[1];   // C0_4 (3,3,3,3)
    float*       out = (float*)d_out;           // (2,3,3,3,3,64,64,64)

    const long total  = (long)NB * G3;               // 524288 voxels
    const int  blocks = (int)(total / THREADS);      // 2048
    alphaC0_42C_kernel<<<blocks, THREADS>>>(a, c0, out);
}

// round 3
// speedup vs baseline: 1.1944x; 1.1944x over previous
#include <cuda_runtime.h>
#include <cstdint>

// Problem constants (fixed by the reference: B=2, G=64)
constexpr int G3      = 64 * 64 * 64;   // 262144 voxels per batch
constexpr int NB      = 2;
constexpr int THREADS = 256;

// Packed f32x2 ops (PTX-only on sm_103a; ptxas never auto-fuses FFMA2 from C++).
__device__ __forceinline__ uint64_t fma2(uint64_t a, uint64_t b, uint64_t c) {
    uint64_t d;
    asm("fma.rn.f32x2 %0, %1, %2, %3;" : "=l"(d) : "l"(a), "l"(b), "l"(c));
    return d;
}
__device__ __forceinline__ uint64_t mul2(uint64_t a, uint64_t b) {
    uint64_t d;
    asm("mul.rn.f32x2 %0, %1, %2;" : "=l"(d) : "l"(a), "l"(b));
    return d;
}

// C_ijkl[b,v] = sum_{m,n,o,p} a[b,m,i,v] a[b,n,j,v] a[b,o,k,v] a[b,p,l,v] C0[m,n,o,p]
// Four staged rank-1 contractions, two voxels per thread, packed f32x2 math:
// 972 FFMA2 per thread (486 FMA-equivalent per voxel of issue).
__global__ __launch_bounds__(THREADS, 2)
void alphaC0_42C_kernel(const float* __restrict__ a,
                        const float* __restrict__ c0,
                        float* __restrict__ out)
{
    // sc0 splatted to both f32x2 lanes so it can be an FFMA2 operand directly.
    __shared__ uint64_t sc0[81];
    if (threadIdx.x < 81) {
        float c = c0[threadIdx.x];
        float2 cc = make_float2(c, c);
        sc0[threadIdx.x] = *reinterpret_cast<uint64_t*>(&cc);
    }
    __syncthreads();

    // Global pair index over the flattened (b, voxel) axis. G3 even -> no
    // pair crosses the batch boundary; v*4 is 8B-aligned -> LDG/STG.64 legal.
    const long pair = (long)blockIdx.x * THREADS + threadIdx.x;
    const long v2   = pair * 2;
    const int  b    = (int)(v2 / G3);
    const long v    = v2 - (long)b * G3;

    // Load the 3x3 per-voxel matrix a[m][i] for both voxels of the pair.
    const float* ap = a + (long)b * 9 * G3 + v;
    uint64_t A[9];
#pragma unroll
    for (int mi = 0; mi < 9; ++mi)
        A[mi] = *reinterpret_cast<const uint64_t*>(ap + (long)mi * G3);

    float* ob = out + (long)b * 81 * G3 + v;

#pragma unroll
    for (int i = 0; i < 3; ++i) {
        // Stage 1: T1[n,o,p] = sum_m A[m,i] * C0[m,n,o,p]
        uint64_t T1[27];
#pragma unroll
        for (int nop = 0; nop < 27; ++nop) {
            uint64_t s = mul2(A[0 * 3 + i], sc0[nop]);
            s = fma2(A[1 * 3 + i], sc0[27 + nop], s);
            s = fma2(A[2 * 3 + i], sc0[54 + nop], s);
            T1[nop] = s;
        }
#pragma unroll
        for (int j = 0; j < 3; ++j) {
            // Stage 2: T2[o,p] = sum_n A[n,j] * T1[n,o,p]
            uint64_t T2[9];
#pragma unroll
            for (int op = 0; op < 9; ++op) {
                uint64_t s = mul2(A[0 * 3 + j], T1[op]);
                s = fma2(A[1 * 3 + j], T1[9 + op], s);
                s = fma2(A[2 * 3 + j], T1[18 + op], s);
                T2[op] = s;
            }
#pragma unroll
            for (int k = 0; k < 3; ++k) {
                // Stage 3: T3[p] = sum_o A[o,k] * T2[o,p]
                uint64_t T3[3];
#pragma unroll
                for (int p = 0; p < 3; ++p) {
                    uint64_t s = mul2(A[0 * 3 + k], T2[p]);
                    s = fma2(A[1 * 3 + k], T2[3 + p], s);
                    s = fma2(A[2 * 3 + k], T2[6 + p], s);
                    T3[p] = s;
                }
#pragma unroll
                for (int l = 0; l < 3; ++l) {
                    // Stage 4: C[i,j,k,l] = sum_p A[p,l] * T3[p]
                    uint64_t r = mul2(A[0 * 3 + l], T3[0]);
                    r = fma2(A[1 * 3 + l], T3[1], r);
                    r = fma2(A[2 * 3 + l], T3[2], r);
                    // Default store: coalesced STG.64, L2 write-back absorbs
                    // the output stream (126 MB L2) — do NOT stream-evict.
                    *reinterpret_cast<uint64_t*>(
                        ob + (long)(((i * 3 + j) * 3 + k) * 3 + l) * G3) = r;
                }
            }
        }
    }
}

extern "C" void kernel_launch(void* const* d_in, const int* in_sizes, int n_in,
                              void* d_out, int out_size)
{
    const float* a   = (const float*)d_in[0];   // alphatensor (2,3,3,64,64,64)
    const float* c0  = (const float*)d_in[1];   // C0_4 (3,3,3,3)
    float*       out = (float*)d_out;           // (2,3,3,3,3,64,64,64)

    const long total_pairs = (long)NB * G3 / 2;            // 262144
    const int  blocks      = (int)(total_pairs / THREADS); // 1024
    alphaC0_42C_kernel<<<blocks, THREADS>>>(a, c0, out);
}

// round 4
// speedup vs baseline: 1.9407x; 1.6248x over previous
#include <cuda_runtime.h>
#include <cstdint>

// Problem constants (fixed by the reference: B=2, G=64)
constexpr int G3      = 64 * 64 * 64;   // 262144 voxels per batch
constexpr int NB      = 2;
constexpr int THREADS = 256;

// Packed f32x2 ops (PTX-only on sm_103a; ptxas never auto-fuses FFMA2 from C++).
__device__ __forceinline__ uint64_t fma2(uint64_t a, uint64_t b, uint64_t c) {
    uint64_t d;
    asm("fma.rn.f32x2 %0, %1, %2, %3;" : "=l"(d) : "l"(a), "l"(b), "l"(c));
    return d;
}
__device__ __forceinline__ uint64_t mul2(uint64_t a, uint64_t b) {
    uint64_t d;
    asm("mul.rn.f32x2 %0, %1, %2;" : "=l"(d) : "l"(a), "l"(b));
    return d;
}

// C_ijkl[b,v] = sum_{m,n,o,p} a[b,m,i,v] a[b,n,j,v] a[b,o,k,v] a[b,p,l,v] C0[m,n,o,p]
// Work split: one thread = one (voxel-pair, i). Total FMA work unchanged
// (stage 1 is per-i); live set shrinks ~3x vs the fused-i version so we get
// 2 CTAs/SM WITHOUT a spill-inducing register cap. Packed f32x2 math halves
// FFMA instruction count: 324 FFMA2 + 81 LDS + 27 STG.64 per thread.
__global__ __launch_bounds__(THREADS, 2)
void alphaC0_42C_kernel(const float* __restrict__ a,
                        const float* __restrict__ c0,
                        float* __restrict__ out)
{
    // sc0 splatted to both f32x2 lanes so it is directly an FFMA2 operand.
    __shared__ uint64_t sc0[81];
    if (threadIdx.x < 81) {
        float c = c0[threadIdx.x];
        float2 cc = make_float2(c, c);
        sc0[threadIdx.x] = *reinterpret_cast<uint64_t*>(&cc);
    }
    __syncthreads();

    const int i = blockIdx.y;  // 0..2

    // Global pair index over the flattened (b, voxel) axis. G3 even -> no
    // pair crosses the batch boundary; v*4 is 8B-aligned -> LDG/STG.64 legal.
    const long pair = (long)blockIdx.x * THREADS + threadIdx.x;
    const long v2   = pair * 2;
    const int  b    = (int)(v2 / G3);
    const long v    = v2 - (long)b * G3;

    // Load the 3x3 per-voxel matrix a[m][i'] for both voxels of the pair.
    const float* ap = a + (long)b * 9 * G3 + v;
    uint64_t A[9];
#pragma unroll
    for (int mi = 0; mi < 9; ++mi)
        A[mi] = *reinterpret_cast<const uint64_t*>(ap + (long)mi * G3);

    // Output slab for this (b, i): out[b][i][j][k][l][v]
    float* ob = out + (long)b * 81 * G3 + (long)i * 27 * G3 + v;

    // Stage 1: T1[n,o,p] = sum_m A[m,i] * C0[m,n,o,p]
    uint64_t T1[27];
#pragma unroll
    for (int nop = 0; nop < 27; ++nop) {
        uint64_t s = mul2(A[0 * 3 + i], sc0[nop]);
        s = fma2(A[1 * 3 + i], sc0[27 + nop], s);
        s = fma2(A[2 * 3 + i], sc0[54 + nop], s);
        T1[nop] = s;
    }
#pragma unroll
    for (int j = 0; j < 3; ++j) {
        // Stage 2: T2[o,p] = sum_n A[n,j] * T1[n,o,p]
        uint64_t T2[9];
#pragma unroll
        for (int op = 0; op < 9; ++op) {
            uint64_t s = mul2(A[0 * 3 + j], T1[op]);
            s = fma2(A[1 * 3 + j], T1[9 + op], s);
            s = fma2(A[2 * 3 + j], T1[18 + op], s);
            T2[op] = s;
        }
#pragma unroll
        for (int k = 0; k < 3; ++k) {
            // Stage 3: T3[p] = sum_o A[o,k] * T2[o,p]
            uint64_t T3[3];
#pragma unroll
            for (int p = 0; p < 3; ++p) {
                uint64_t s = mul2(A[0 * 3 + k], T2[p]);
                s = fma2(A[1 * 3 + k], T2[3 + p], s);
                s = fma2(A[2 * 3 + k], T2[6 + p], s);
                T3[p] = s;
            }
#pragma unroll
            for (int l = 0; l < 3; ++l) {
                // Stage 4: C[i,j,k,l] = sum_p A[p,l] * T3[p]
                uint64_t r = mul2(A[0 * 3 + l], T3[0]);
                r = fma2(A[1 * 3 + l], T3[1], r);
                r = fma2(A[2 * 3 + l], T3[2], r);
                // Default store: coalesced STG.64, L2 write-back absorbs the
                // output stream (126 MB L2) — do NOT stream-evict.
                *reinterpret_cast<uint64_t*>(
                    ob + (long)((j * 3 + k) * 3 + l) * G3) = r;
            }
        }
    }
}

extern "C" void kernel_launch(void* const* d_in, const int* in_sizes, int n_in,
                              void* d_out, int out_size)
{
    const float* a   = (const float*)d_in[0];   // alphatensor (2,3,3,64,64,64)
    const float* c0  = (const float*)d_in[1];   // C0_4 (3,3,3,3)
    float*       out = (float*)d_out;           // (2,3,3,3,3,64,64,64)

    const long total_pairs = (long)NB * G3 / 2;              // 262144
    dim3 grid((unsigned)(total_pairs / THREADS), 3, 1);      // (1024, 3)
    alphaC0_42C_kernel<<<grid, THREADS>>>(a, c0, out);
}